// round 2
// baseline (speedup 1.0000x reference)
#include <cuda_runtime.h>
#include <math.h>

#define D_MODEL 1024
#define N_HEADS 16
#define D_KH    64
#define BATCH   4
#define SEQ     2048
#define M_ROWS  (BATCH * SEQ)   // 8192

// Scratch (device globals — no allocation allowed in kernel_launch)
__device__ float g_Q[(size_t)BATCH * N_HEADS * SEQ * D_KH];
__device__ float g_K[(size_t)BATCH * N_HEADS * SEQ * D_KH];
__device__ float g_V[(size_t)BATCH * N_HEADS * SEQ * D_KH];
__device__ float g_ctx[(size_t)M_ROWS * D_MODEL];

// ---------------------------------------------------------------------------
// GEMM: C = A[M,K] @ W[N,K]^T + bias[N]
// 128x128 tile, BK=8, 256 threads, 8x8 per-thread register tile.
// scatter=1: write into [B,H,S,Dk] layout (QKV projections)
// scatter=0: write row-major [M,N] (output projection / final output)
// ---------------------------------------------------------------------------
__global__ __launch_bounds__(256) void gemm_bias(
    const float* __restrict__ A, const float* __restrict__ W,
    const float* __restrict__ bias, float* __restrict__ C, int scatter)
{
    const int K = D_MODEL;
    const int N = D_MODEL;
    __shared__ float As[8][128];
    __shared__ float Bs[8][128];

    int tid = threadIdx.x;
    int tx = tid & 15;        // 0..15 -> 8 N-cols each
    int ty = tid >> 4;        // 0..15 -> 8 M-rows each

    const float* Ab = A + (size_t)blockIdx.y * 128 * K;
    const float* Wb = W + (size_t)blockIdx.x * 128 * K;

    int lr = tid >> 1;            // row within tile (0..127)
    int lk = (tid & 1) << 2;      // k offset (0 or 4)

    float acc[8][8];
#pragma unroll
    for (int i = 0; i < 8; i++)
#pragma unroll
        for (int j = 0; j < 8; j++) acc[i][j] = 0.f;

    for (int k0 = 0; k0 < K; k0 += 8) {
        float4 av = *(const float4*)(Ab + (size_t)lr * K + k0 + lk);
        float4 bv = *(const float4*)(Wb + (size_t)lr * K + k0 + lk);
        As[lk + 0][lr] = av.x; As[lk + 1][lr] = av.y;
        As[lk + 2][lr] = av.z; As[lk + 3][lr] = av.w;
        Bs[lk + 0][lr] = bv.x; Bs[lk + 1][lr] = bv.y;
        Bs[lk + 2][lr] = bv.z; Bs[lk + 3][lr] = bv.w;
        __syncthreads();
#pragma unroll
        for (int kk = 0; kk < 8; kk++) {
            float a[8], b[8];
            *(float4*)&a[0] = *(const float4*)&As[kk][ty * 8];
            *(float4*)&a[4] = *(const float4*)&As[kk][ty * 8 + 4];
            *(float4*)&b[0] = *(const float4*)&Bs[kk][tx * 8];
            *(float4*)&b[4] = *(const float4*)&Bs[kk][tx * 8 + 4];
#pragma unroll
            for (int i = 0; i < 8; i++)
#pragma unroll
                for (int j = 0; j < 8; j++)
                    acc[i][j] += a[i] * b[j];
        }
        __syncthreads();
    }

    int gm = blockIdx.y * 128 + ty * 8;
    int gn = blockIdx.x * 128 + tx * 8;
    if (scatter) {
        // n -> (h, dk); m -> (b, s); write to [B,H,S,Dk]
        int h = gn >> 6;          // gn is a multiple of 8, so h is constant over j
        int dk = gn & 63;
#pragma unroll
        for (int i = 0; i < 8; i++) {
            int m = gm + i;
            int b = m >> 11;
            int s = m & 2047;
            float* dst = C + ((((size_t)b * N_HEADS + h) * SEQ) + s) * D_KH + dk;
#pragma unroll
            for (int j = 0; j < 8; j++)
                dst[j] = acc[i][j] + bias[gn + j];
        }
    } else {
#pragma unroll
        for (int i = 0; i < 8; i++) {
            int m = gm + i;
#pragma unroll
            for (int j = 0; j < 8; j++)
                C[(size_t)m * N + gn + j] = acc[i][j] + bias[gn + j];
        }
    }
}

// ---------------------------------------------------------------------------
// Flash-attention style: per (b,h), 64-query tile per block, iterate 64-key
// tiles. 256 threads; thread (ty,tx) owns rows ty*4+i and cols tx+16*j
// (interleaved column mapping for conflict-free smem access).
// Online softmax in fp32. Writes ctx in [B,S,D] layout for the output GEMM.
// ---------------------------------------------------------------------------
#define QS_STRIDE 65

__global__ __launch_bounds__(256) void attn_kernel(
    const float* __restrict__ Q, const float* __restrict__ K,
    const float* __restrict__ V, float* __restrict__ ctx)
{
    extern __shared__ float sm[];
    float* Qs = sm;                       // 64 x 65
    float* Ks = sm + 64 * QS_STRIDE;      // 64 x 65
    float* Ps = sm + 2 * 64 * QS_STRIDE;  // 64 x 65
    float* Vs = sm + 3 * 64 * QS_STRIDE;  // 64 x 64

    int tid = threadIdx.x;
    int tx = tid & 15;
    int ty = tid >> 4;
    int bh = blockIdx.y;            // b*16 + h
    int b = bh >> 4;
    int h = bh & 15;
    int qt = blockIdx.x;

    const float* Qp = Q + ((size_t)bh * SEQ + qt * 64) * D_KH;
    const float* Kp = K + (size_t)bh * SEQ * D_KH;
    const float* Vp = V + (size_t)bh * SEQ * D_KH;

    // Load Q tile (64x64), fold in 1/sqrt(Dk) = 1/8
#pragma unroll
    for (int it = 0; it < 4; it++) {
        int i = tid + it * 256;          // float4 slot index, 0..1023
        int r = i >> 4;
        int c = (i & 15) << 2;
        float4 v = *(const float4*)(Qp + r * D_KH + c);
        float* q = &Qs[r * QS_STRIDE + c];
        q[0] = v.x * 0.125f; q[1] = v.y * 0.125f;
        q[2] = v.z * 0.125f; q[3] = v.w * 0.125f;
    }

    float m_i[4], l_i[4], o[4][4];
#pragma unroll
    for (int i = 0; i < 4; i++) {
        m_i[i] = -1e30f; l_i[i] = 0.f;
#pragma unroll
        for (int c = 0; c < 4; c++) o[i][c] = 0.f;
    }

    for (int kt = 0; kt < SEQ / 64; kt++) {
        // Load K,V tiles
#pragma unroll
        for (int it = 0; it < 4; it++) {
            int i = tid + it * 256;
            int r = i >> 4;
            int c = (i & 15) << 2;
            float4 kv = *(const float4*)(Kp + ((size_t)kt * 64 + r) * D_KH + c);
            float4 vv = *(const float4*)(Vp + ((size_t)kt * 64 + r) * D_KH + c);
            float* kd = &Ks[r * QS_STRIDE + c];
            kd[0] = kv.x; kd[1] = kv.y; kd[2] = kv.z; kd[3] = kv.w;
            *(float4*)&Vs[r * 64 + c] = vv;
        }
        __syncthreads();

        // Scores: s[i][j] = Q[row_i] . K[col_j], rows = ty*4+i, cols = tx+16*j
        float s[4][4];
#pragma unroll
        for (int i = 0; i < 4; i++)
#pragma unroll
            for (int j = 0; j < 4; j++) s[i][j] = 0.f;

#pragma unroll 4
        for (int d = 0; d < 64; d++) {
            float a[4], bb[4];
#pragma unroll
            for (int i = 0; i < 4; i++) a[i] = Qs[(ty * 4 + i) * QS_STRIDE + d];
#pragma unroll
            for (int j = 0; j < 4; j++) bb[j] = Ks[(tx + 16 * j) * QS_STRIDE + d];
#pragma unroll
            for (int i = 0; i < 4; i++)
#pragma unroll
                for (int j = 0; j < 4; j++)
                    s[i][j] += a[i] * bb[j];
        }

        // Online softmax (row reduction across the 16 tx lanes — same half-warp)
#pragma unroll
        for (int i = 0; i < 4; i++) {
            float mx = fmaxf(fmaxf(s[i][0], s[i][1]), fmaxf(s[i][2], s[i][3]));
            mx = fmaxf(mx, __shfl_xor_sync(0xffffffffu, mx, 8));
            mx = fmaxf(mx, __shfl_xor_sync(0xffffffffu, mx, 4));
            mx = fmaxf(mx, __shfl_xor_sync(0xffffffffu, mx, 2));
            mx = fmaxf(mx, __shfl_xor_sync(0xffffffffu, mx, 1));
            float mnew = fmaxf(m_i[i], mx);
            float alpha = __expf(m_i[i] - mnew);
            float p0 = __expf(s[i][0] - mnew);
            float p1 = __expf(s[i][1] - mnew);
            float p2 = __expf(s[i][2] - mnew);
            float p3 = __expf(s[i][3] - mnew);
            float* pr = &Ps[(ty * 4 + i) * QS_STRIDE];
            pr[tx +  0] = p0;
            pr[tx + 16] = p1;
            pr[tx + 32] = p2;
            pr[tx + 48] = p3;
            float ls = (p0 + p1) + (p2 + p3);
            ls += __shfl_xor_sync(0xffffffffu, ls, 8);
            ls += __shfl_xor_sync(0xffffffffu, ls, 4);
            ls += __shfl_xor_sync(0xffffffffu, ls, 2);
            ls += __shfl_xor_sync(0xffffffffu, ls, 1);
            l_i[i] = l_i[i] * alpha + ls;
            m_i[i] = mnew;
#pragma unroll
            for (int c = 0; c < 4; c++) o[i][c] *= alpha;
        }
        __syncthreads();

        // O += P @ V : rows ty*4+i, dk cols tx+16*c
#pragma unroll 4
        for (int jj = 0; jj < 64; jj++) {
            float p[4], v[4];
#pragma unroll
            for (int i = 0; i < 4; i++) p[i] = Ps[(ty * 4 + i) * QS_STRIDE + jj];
#pragma unroll
            for (int c = 0; c < 4; c++) v[c] = Vs[jj * 64 + tx + 16 * c];
#pragma unroll
            for (int i = 0; i < 4; i++)
#pragma unroll
                for (int c = 0; c < 4; c++)
                    o[i][c] += p[i] * v[c];
        }
        __syncthreads();
    }

    // Epilogue: write ctx in [B, S, D_MODEL] layout
    float* cb = ctx + (size_t)b * SEQ * D_MODEL + (size_t)h * D_KH;
#pragma unroll
    for (int i = 0; i < 4; i++) {
        int srow = qt * 64 + ty * 4 + i;
        float inv = 1.f / l_i[i];
        float* dst = cb + (size_t)srow * D_MODEL;
        dst[tx +  0] = o[i][0] * inv;
        dst[tx + 16] = o[i][1] * inv;
        dst[tx + 32] = o[i][2] * inv;
        dst[tx + 48] = o[i][3] * inv;
    }
}

// ---------------------------------------------------------------------------
extern "C" void kernel_launch(void* const* d_in, const int* in_sizes, int n_in,
                              void* d_out, int out_size)
{
    const float* x  = (const float*)d_in[0];
    const float* Wq = (const float*)d_in[1];
    const float* bq = (const float*)d_in[2];
    const float* Wk = (const float*)d_in[3];
    const float* bk = (const float*)d_in[4];
    const float* Wv = (const float*)d_in[5];
    const float* bv = (const float*)d_in[6];
    const float* Wo = (const float*)d_in[7];
    const float* bo = (const float*)d_in[8];
    float* out = (float*)d_out;

    float *Qd, *Kd, *Vd, *Cd;
    cudaGetSymbolAddress((void**)&Qd, g_Q);
    cudaGetSymbolAddress((void**)&Kd, g_K);
    cudaGetSymbolAddress((void**)&Vd, g_V);
    cudaGetSymbolAddress((void**)&Cd, g_ctx);

    dim3 gg(D_MODEL / 128, M_ROWS / 128);
    gemm_bias<<<gg, 256>>>(x, Wq, bq, Qd, 1);
    gemm_bias<<<gg, 256>>>(x, Wk, bk, Kd, 1);
    gemm_bias<<<gg, 256>>>(x, Wv, bv, Vd, 1);

    size_t smem = (size_t)(3 * 64 * QS_STRIDE + 64 * 64) * sizeof(float);
    cudaFuncSetAttribute(attn_kernel, cudaFuncAttributeMaxDynamicSharedMemorySize,
                         (int)smem);
    attn_kernel<<<dim3(SEQ / 64, BATCH * N_HEADS), 256, smem>>>(Qd, Kd, Vd, Cd);

    gemm_bias<<<gg, 256>>>(Cd, Wo, bo, out, 0);
}

// round 3
// speedup vs baseline: 1.0025x; 1.0025x over previous
#include <cuda_runtime.h>
#include <math.h>

#define D_MODEL 1024
#define N_HEADS 16
#define D_KH    64
#define BATCH   4
#define SEQ     2048
#define M_ROWS  (BATCH * SEQ)   // 8192

// Scratch (device globals — no allocation allowed in kernel_launch)
__device__ float g_Q[(size_t)BATCH * N_HEADS * SEQ * D_KH];
__device__ float g_K[(size_t)BATCH * N_HEADS * SEQ * D_KH];
__device__ float g_V[(size_t)BATCH * N_HEADS * SEQ * D_KH];
__device__ float g_ctx[(size_t)M_ROWS * D_MODEL];

// ---------------------------------------------------------------------------
// GEMM: C = A[M,K] @ W[N,K]^T + bias[N]
// 128x128 tile, BK=8, 256 threads, 8x8 per-thread register tile.
// scatter=1: write into [B,H,S,Dk] layout (QKV projections)
// scatter=0: write row-major [M,N] (output projection / final output)
// ---------------------------------------------------------------------------
__global__ __launch_bounds__(256) void gemm_bias(
    const float* __restrict__ A, const float* __restrict__ W,
    const float* __restrict__ bias, float* __restrict__ C, int scatter)
{
    const int K = D_MODEL;
    const int N = D_MODEL;
    __shared__ float As[8][128];
    __shared__ float Bs[8][128];

    int tid = threadIdx.x;
    int tx = tid & 15;        // 0..15 -> 8 N-cols each
    int ty = tid >> 4;        // 0..15 -> 8 M-rows each

    const float* Ab = A + (size_t)blockIdx.y * 128 * K;
    const float* Wb = W + (size_t)blockIdx.x * 128 * K;

    int lr = tid >> 1;            // row within tile (0..127)
    int lk = (tid & 1) << 2;      // k offset (0 or 4)

    float acc[8][8];
#pragma unroll
    for (int i = 0; i < 8; i++)
#pragma unroll
        for (int j = 0; j < 8; j++) acc[i][j] = 0.f;

    for (int k0 = 0; k0 < K; k0 += 8) {
        float4 av = *(const float4*)(Ab + (size_t)lr * K + k0 + lk);
        float4 bv = *(const float4*)(Wb + (size_t)lr * K + k0 + lk);
        As[lk + 0][lr] = av.x; As[lk + 1][lr] = av.y;
        As[lk + 2][lr] = av.z; As[lk + 3][lr] = av.w;
        Bs[lk + 0][lr] = bv.x; Bs[lk + 1][lr] = bv.y;
        Bs[lk + 2][lr] = bv.z; Bs[lk + 3][lr] = bv.w;
        __syncthreads();
#pragma unroll
        for (int kk = 0; kk < 8; kk++) {
            float a[8], b[8];
            *(float4*)&a[0] = *(const float4*)&As[kk][ty * 8];
            *(float4*)&a[4] = *(const float4*)&As[kk][ty * 8 + 4];
            *(float4*)&b[0] = *(const float4*)&Bs[kk][tx * 8];
            *(float4*)&b[4] = *(const float4*)&Bs[kk][tx * 8 + 4];
#pragma unroll
            for (int i = 0; i < 8; i++)
#pragma unroll
                for (int j = 0; j < 8; j++)
                    acc[i][j] += a[i] * b[j];
        }
        __syncthreads();
    }

    int gm = blockIdx.y * 128 + ty * 8;
    int gn = blockIdx.x * 128 + tx * 8;
    if (scatter) {
        // n -> (h, dk); m -> (b, s); write to [B,H,S,Dk]
        int h = gn >> 6;          // gn is a multiple of 8, so h is constant over j
        int dk = gn & 63;
#pragma unroll
        for (int i = 0; i < 8; i++) {
            int m = gm + i;
            int b = m >> 11;
            int s = m & 2047;
            float* dst = C + ((((size_t)b * N_HEADS + h) * SEQ) + s) * D_KH + dk;
#pragma unroll
            for (int j = 0; j < 8; j++)
                dst[j] = acc[i][j] + bias[gn + j];
        }
    } else {
#pragma unroll
        for (int i = 0; i < 8; i++) {
            int m = gm + i;
#pragma unroll
            for (int j = 0; j < 8; j++)
                C[(size_t)m * N + gn + j] = acc[i][j] + bias[gn + j];
        }
    }
}

// ---------------------------------------------------------------------------
// Flash-attention style: per (b,h), 64-query tile per block, iterate 64-key
// tiles. 256 threads; thread (ty,tx) owns rows ty*4+i and cols tx+16*j
// (interleaved column mapping for conflict-free smem access).
// Online softmax in fp32. Writes ctx in [B,S,D] layout for the output GEMM.
// ---------------------------------------------------------------------------
#define QS_STRIDE 65

__global__ __launch_bounds__(256) void attn_kernel(
    const float* __restrict__ Q, const float* __restrict__ K,
    const float* __restrict__ V, float* __restrict__ ctx)
{
    extern __shared__ float sm[];
    float* Qs = sm;                       // 64 x 65
    float* Ks = sm + 64 * QS_STRIDE;      // 64 x 65
    float* Ps = sm + 2 * 64 * QS_STRIDE;  // 64 x 65
    float* Vs = sm + 3 * 64 * QS_STRIDE;  // 64 x 64

    int tid = threadIdx.x;
    int tx = tid & 15;
    int ty = tid >> 4;
    int bh = blockIdx.y;            // b*16 + h
    int b = bh >> 4;
    int h = bh & 15;
    int qt = blockIdx.x;

    const float* Qp = Q + ((size_t)bh * SEQ + qt * 64) * D_KH;
    const float* Kp = K + (size_t)bh * SEQ * D_KH;
    const float* Vp = V + (size_t)bh * SEQ * D_KH;

    // Load Q tile (64x64), fold in 1/sqrt(Dk) = 1/8
#pragma unroll
    for (int it = 0; it < 4; it++) {
        int i = tid + it * 256;          // float4 slot index, 0..1023
        int r = i >> 4;
        int c = (i & 15) << 2;
        float4 v = *(const float4*)(Qp + r * D_KH + c);
        float* q = &Qs[r * QS_STRIDE + c];
        q[0] = v.x * 0.125f; q[1] = v.y * 0.125f;
        q[2] = v.z * 0.125f; q[3] = v.w * 0.125f;
    }

    float m_i[4], l_i[4], o[4][4];
#pragma unroll
    for (int i = 0; i < 4; i++) {
        m_i[i] = -1e30f; l_i[i] = 0.f;
#pragma unroll
        for (int c = 0; c < 4; c++) o[i][c] = 0.f;
    }

    for (int kt = 0; kt < SEQ / 64; kt++) {
        // Load K,V tiles
#pragma unroll
        for (int it = 0; it < 4; it++) {
            int i = tid + it * 256;
            int r = i >> 4;
            int c = (i & 15) << 2;
            float4 kv = *(const float4*)(Kp + ((size_t)kt * 64 + r) * D_KH + c);
            float4 vv = *(const float4*)(Vp + ((size_t)kt * 64 + r) * D_KH + c);
            float* kd = &Ks[r * QS_STRIDE + c];
            kd[0] = kv.x; kd[1] = kv.y; kd[2] = kv.z; kd[3] = kv.w;
            *(float4*)&Vs[r * 64 + c] = vv;
        }
        __syncthreads();

        // Scores: s[i][j] = Q[row_i] . K[col_j], rows = ty*4+i, cols = tx+16*j
        float s[4][4];
#pragma unroll
        for (int i = 0; i < 4; i++)
#pragma unroll
            for (int j = 0; j < 4; j++) s[i][j] = 0.f;

#pragma unroll 4
        for (int d = 0; d < 64; d++) {
            float a[4], bb[4];
#pragma unroll
            for (int i = 0; i < 4; i++) a[i] = Qs[(ty * 4 + i) * QS_STRIDE + d];
#pragma unroll
            for (int j = 0; j < 4; j++) bb[j] = Ks[(tx + 16 * j) * QS_STRIDE + d];
#pragma unroll
            for (int i = 0; i < 4; i++)
#pragma unroll
                for (int j = 0; j < 4; j++)
                    s[i][j] += a[i] * bb[j];
        }

        // Online softmax (row reduction across the 16 tx lanes — same half-warp)
#pragma unroll
        for (int i = 0; i < 4; i++) {
            float mx = fmaxf(fmaxf(s[i][0], s[i][1]), fmaxf(s[i][2], s[i][3]));
            mx = fmaxf(mx, __shfl_xor_sync(0xffffffffu, mx, 8));
            mx = fmaxf(mx, __shfl_xor_sync(0xffffffffu, mx, 4));
            mx = fmaxf(mx, __shfl_xor_sync(0xffffffffu, mx, 2));
            mx = fmaxf(mx, __shfl_xor_sync(0xffffffffu, mx, 1));
            float mnew = fmaxf(m_i[i], mx);
            float alpha = __expf(m_i[i] - mnew);
            float p0 = __expf(s[i][0] - mnew);
            float p1 = __expf(s[i][1] - mnew);
            float p2 = __expf(s[i][2] - mnew);
            float p3 = __expf(s[i][3] - mnew);
            float* pr = &Ps[(ty * 4 + i) * QS_STRIDE];
            pr[tx +  0] = p0;
            pr[tx + 16] = p1;
            pr[tx + 32] = p2;
            pr[tx + 48] = p3;
            float ls = (p0 + p1) + (p2 + p3);
            ls += __shfl_xor_sync(0xffffffffu, ls, 8);
            ls += __shfl_xor_sync(0xffffffffu, ls, 4);
            ls += __shfl_xor_sync(0xffffffffu, ls, 2);
            ls += __shfl_xor_sync(0xffffffffu, ls, 1);
            l_i[i] = l_i[i] * alpha + ls;
            m_i[i] = mnew;
#pragma unroll
            for (int c = 0; c < 4; c++) o[i][c] *= alpha;
        }
        __syncthreads();

        // O += P @ V : rows ty*4+i, dk cols tx+16*c
#pragma unroll 4
        for (int jj = 0; jj < 64; jj++) {
            float p[4], v[4];
#pragma unroll
            for (int i = 0; i < 4; i++) p[i] = Ps[(ty * 4 + i) * QS_STRIDE + jj];
#pragma unroll
            for (int c = 0; c < 4; c++) v[c] = Vs[jj * 64 + tx + 16 * c];
#pragma unroll
            for (int i = 0; i < 4; i++)
#pragma unroll
                for (int c = 0; c < 4; c++)
                    o[i][c] += p[i] * v[c];
        }
        __syncthreads();
    }

    // Epilogue: write ctx in [B, S, D_MODEL] layout
    float* cb = ctx + (size_t)b * SEQ * D_MODEL + (size_t)h * D_KH;
#pragma unroll
    for (int i = 0; i < 4; i++) {
        int srow = qt * 64 + ty * 4 + i;
        float inv = 1.f / l_i[i];
        float* dst = cb + (size_t)srow * D_MODEL;
        dst[tx +  0] = o[i][0] * inv;
        dst[tx + 16] = o[i][1] * inv;
        dst[tx + 32] = o[i][2] * inv;
        dst[tx + 48] = o[i][3] * inv;
    }
}

// ---------------------------------------------------------------------------
extern "C" void kernel_launch(void* const* d_in, const int* in_sizes, int n_in,
                              void* d_out, int out_size)
{
    const float* x  = (const float*)d_in[0];
    const float* Wq = (const float*)d_in[1];
    const float* bq = (const float*)d_in[2];
    const float* Wk = (const float*)d_in[3];
    const float* bk = (const float*)d_in[4];
    const float* Wv = (const float*)d_in[5];
    const float* bv = (const float*)d_in[6];
    const float* Wo = (const float*)d_in[7];
    const float* bo = (const float*)d_in[8];
    float* out = (float*)d_out;

    float *Qd, *Kd, *Vd, *Cd;
    cudaGetSymbolAddress((void**)&Qd, g_Q);
    cudaGetSymbolAddress((void**)&Kd, g_K);
    cudaGetSymbolAddress((void**)&Vd, g_V);
    cudaGetSymbolAddress((void**)&Cd, g_ctx);

    dim3 gg(D_MODEL / 128, M_ROWS / 128);
    gemm_bias<<<gg, 256>>>(x, Wq, bq, Qd, 1);
    gemm_bias<<<gg, 256>>>(x, Wk, bk, Kd, 1);
    gemm_bias<<<gg, 256>>>(x, Wv, bv, Vd, 1);

    size_t smem = (size_t)(3 * 64 * QS_STRIDE + 64 * 64) * sizeof(float);
    cudaFuncSetAttribute(attn_kernel, cudaFuncAttributeMaxDynamicSharedMemorySize,
                         (int)smem);
    attn_kernel<<<dim3(SEQ / 64, BATCH * N_HEADS), 256, smem>>>(Qd, Kd, Vd, Cd);

    gemm_bias<<<gg, 256>>>(Cd, Wo, bo, out, 0);
}